// round 5
// baseline (speedup 1.0000x reference)
#include <cuda_runtime.h>
#include <math.h>

#define D  4096
#define K2 8192
#define KS 32          // split-K chunks (512-block grid saturates HBM — R3 lesson)
#define KC (K2 / KS)   // 256 rows per chunk

// ---------------- scratch (no device allocation allowed) ----------------
__device__ float    g_partial[4 * KS * D];   // split-K partial sums (2 MB, L2-resident)
__device__ float    g_qa[4 * D];             // quantized gate activations (f, i, c, o)
__device__ float    g_scale, g_rscale;       // concat quant scale + reciprocal
__device__ unsigned g_done;                  // gate-block completion counter

// ---------------- helpers ----------------
__device__ __forceinline__ float mkscale(float maxabs) {
    // matches jnp.where(max_abs > 0, max_abs / 127.0, 1.0) in fp32
    return (maxabs > 0.0f) ? (maxabs / 127.0f) : 1.0f;
}

// quantize with precomputed reciprocal (one division per scale, FMA per element)
__device__ __forceinline__ float qvalr(float x, float scale, float rscale) {
    float r = rintf(x * rscale);
    r = fminf(fmaxf(r, -127.0f), 127.0f);
    return r * scale;
}

__device__ __forceinline__ float sigm(float x) {
    return __fdividef(1.0f, 1.0f + __expf(-x));
}

// Block-wide max (signed-safe). blockDim.x multiple of 32.
__device__ __forceinline__ float blockMax(float v) {
    __shared__ float s[32];
    const unsigned full = 0xffffffffu;
    #pragma unroll
    for (int o = 16; o; o >>= 1) v = fmaxf(v, __shfl_xor_sync(full, v, o));
    int lane = threadIdx.x & 31;
    int w    = threadIdx.x >> 5;
    int nw   = (blockDim.x + 31) >> 5;
    if (lane == 0) s[w] = v;
    __syncthreads();
    if (w == 0) {
        float r = (lane < nw) ? s[lane] : -INFINITY;
        #pragma unroll
        for (int o = 16; o; o >>= 1) r = fmaxf(r, __shfl_xor_sync(full, r, o));
        if (lane == 0) s[0] = r;
    }
    __syncthreads();
    float out = s[0];
    __syncthreads();
    return out;
}

// Two block-wide maxes sharing one set of barriers.
__device__ __forceinline__ float2 blockMax2(float a, float b) {
    __shared__ float sa[32], sb[32];
    const unsigned full = 0xffffffffu;
    #pragma unroll
    for (int o = 16; o; o >>= 1) {
        a = fmaxf(a, __shfl_xor_sync(full, a, o));
        b = fmaxf(b, __shfl_xor_sync(full, b, o));
    }
    int lane = threadIdx.x & 31;
    int w    = threadIdx.x >> 5;
    int nw   = (blockDim.x + 31) >> 5;
    if (lane == 0) { sa[w] = a; sb[w] = b; }
    __syncthreads();
    if (w == 0) {
        float ra = (lane < nw) ? sa[lane] : -INFINITY;
        float rb = (lane < nw) ? sb[lane] : -INFINITY;
        #pragma unroll
        for (int o = 16; o; o >>= 1) {
            ra = fmaxf(ra, __shfl_xor_sync(full, ra, o));
            rb = fmaxf(rb, __shfl_xor_sync(full, rb, o));
        }
        if (lane == 0) { sa[0] = ra; sb[0] = rb; }
    }
    __syncthreads();
    float2 out = make_float2(sa[0], sb[0]);
    __syncthreads();
    return out;
}

__device__ __forceinline__ float max4abs(float4 v) {
    return fmaxf(fmaxf(fabsf(v.x), fabsf(v.y)), fmaxf(fabsf(v.z), fabsf(v.w)));
}

// ---------------- kernel 1: concat scale (max-reduce only) + counter reset ----------------
__global__ void prep_kernel(const float* __restrict__ x, const float* __restrict__ h) {
    int tid = threadIdx.x;                  // 1024 threads
    float lm = 0.0f;
    #pragma unroll
    for (int j = 0; j < 8; j++) {
        int i = tid + j * 1024;             // 0..8191
        float v = (i < D) ? h[i] : x[i - D];
        lm = fmaxf(lm, fabsf(v));
    }
    float s = mkscale(blockMax(lm));
    if (tid == 0) {
        g_scale  = s;
        g_rscale = 1.0f / s;
        g_done   = 0u;                      // reset handshake for this graph replay
    }
}

// ---------------- kernel 2: split-K GEMV (HBM-bound streamer) ----------------
// grid = (4 n-chunks, 32 k-chunks, 4 gates) = 512 blocks x 256 threads.
// Prologue is cheap: one scalar scale load + quantize own 256-row x-chunk.
__global__ void __launch_bounds__(256) gemv_kernel(
    const float* __restrict__ x,  const float* __restrict__ h,
    const float* __restrict__ Wf, const float* __restrict__ Wi,
    const float* __restrict__ Wc, const float* __restrict__ Wo)
{
    __shared__ float xs[KC];
    const int g  = blockIdx.z;                              // gate
    const int kc = blockIdx.y;                              // k-chunk
    const int n0 = blockIdx.x * 1024 + threadIdx.x * 4;     // 4 cols per thread
    const int k0 = kc * KC;

    const float* W = (g == 0) ? Wf : (g == 1) ? Wi : (g == 2) ? Wc : Wo;

    // quantize this block's k-chunk of the concat (KC == blockDim.x == 256)
    {
        float s  = g_scale;
        float rs = g_rscale;
        int gi = k0 + threadIdx.x;
        float v = (gi < D) ? h[gi] : x[gi - D];
        xs[threadIdx.x] = qvalr(v, s, rs);
    }
    __syncthreads();

    const float4* p = reinterpret_cast<const float4*>(W + (size_t)k0 * D + n0);
    const int rowstride = D / 4;

    float4 acc = make_float4(0.f, 0.f, 0.f, 0.f);
    #pragma unroll 8
    for (int i = 0; i < KC; i++) {
        float4 w = __ldcs(p + (size_t)i * rowstride);   // streaming: read-once weights
        float  xv = xs[i];
        acc.x = fmaf(xv, w.x, acc.x);
        acc.y = fmaf(xv, w.y, acc.y);
        acc.z = fmaf(xv, w.z, acc.z);
        acc.w = fmaf(xv, w.w, acc.w);
    }
    *reinterpret_cast<float4*>(&g_partial[(size_t)(g * KS + kc) * D + n0]) = acc;
}

// ---------------- kernel 3: gate chain (4 blocks) + fused tail in last-done block ----
__global__ void gate_tail_kernel(const float* __restrict__ bf, const float* __restrict__ bi,
                                 const float* __restrict__ bc, const float* __restrict__ bo,
                                 const float* __restrict__ c_in, float* __restrict__ out)
{
    const int g = blockIdx.x;
    const float* b = (g == 0) ? bf : (g == 1) ? bi : (g == 2) ? bc : bo;

    // --- per-gate: split-K reduce (L2-resident), quantized linear, activation ---
    const float4* pp = reinterpret_cast<const float4*>(g_partial)
                     + (size_t)g * KS * (D / 4) + threadIdx.x;
    float4 acc = make_float4(0.f, 0.f, 0.f, 0.f);
    #pragma unroll
    for (int ks = 0; ks < KS; ks++) {
        float4 v = pp[(size_t)ks * (D / 4)];
        acc.x += v.x; acc.y += v.y; acc.z += v.z; acc.w += v.w;
    }
    float4 bv = reinterpret_cast<const float4*>(b)[threadIdx.x];

    float2 mm = blockMax2(max4abs(acc), max4abs(bv));
    float sm = mkscale(mm.x), rsm = 1.0f / sm;     // Q(x@w) scale
    float sb = mkscale(mm.y), rsb = 1.0f / sb;     // Q(b) scale

    float y[4] = { qvalr(acc.x, sm, rsm) + qvalr(bv.x, sb, rsb),
                   qvalr(acc.y, sm, rsm) + qvalr(bv.y, sb, rsb),
                   qvalr(acc.z, sm, rsm) + qvalr(bv.z, sb, rsb),
                   qvalr(acc.w, sm, rsm) + qvalr(bv.w, sb, rsb) };

    float lmax = fmaxf(fmaxf(y[0], y[1]), fmaxf(y[2], y[3]));
    float lmin = fminf(fminf(y[0], y[1]), fminf(y[2], y[3]));
    float2 ym = blockMax2(lmax, -lmin);            // (max y, -min y)
    float sy  = mkscale(fmaxf(ym.x, ym.y));
    float rsy = 1.0f / sy;

    // analytic activation scale (monotone functions -> evaluate at argmax)
    float sa;
    if (g == 2) {
        sa = mkscale(tanhf(qvalr(fmaxf(ym.x, ym.y), sy, rsy)));  // tanh odd+monotone
    } else {
        sa = mkscale(sigm(qvalr(ym.x, sy, rsy)));                // sigmoid increasing, >0
    }
    float rsa = 1.0f / sa;

    float4 qa;
    float* qp = &qa.x;
    #pragma unroll
    for (int j = 0; j < 4; j++) {
        float yq = qvalr(y[j], sy, rsy);                 // Q(Q(x@w)+Q(b))
        float a  = (g == 2) ? tanhf(yq) : sigm(yq);
        qp[j] = qvalr(a, sa, rsa);                       // Q(activation)
    }
    reinterpret_cast<float4*>(g_qa)[(size_t)g * (D / 4) + threadIdx.x] = qa;

    // --- last-done handshake: the 4th block to finish runs the tail inline ---
    __shared__ unsigned s_ticket;
    __threadfence();                 // make this block's qa globally visible
    __syncthreads();                 // all threads' qa written + fenced
    if (threadIdx.x == 0) s_ticket = atomicAdd(&g_done, 1u);
    __syncthreads();
    if (s_ticket != 3u) return;      // not last: done
    __threadfence();                 // acquire: other blocks' qa now visible

    // --- tail: LSTM state update (this block only) ---
    const int t = threadIdx.x;
    const float4* qa4 = reinterpret_cast<const float4*>(g_qa);
    float4 zf = qa4[0 * (D / 4) + t];
    float4 zi = qa4[1 * (D / 4) + t];
    float4 z  = qa4[2 * (D / 4) + t];
    float4 zo = qa4[3 * (D / 4) + t];
    float4 cv = reinterpret_cast<const float4*>(c_in)[t];

    float mem[4] = { z.x * zi.x,  z.y * zi.y,  z.z * zi.z,  z.w * zi.w };
    float cf [4] = { cv.x * zf.x, cv.y * zf.y, cv.z * zf.z, cv.w * zf.w };

    float lm = 0.f, lc = 0.f;
    #pragma unroll
    for (int j = 0; j < 4; j++) { lm = fmaxf(lm, fabsf(mem[j])); lc = fmaxf(lc, fabsf(cf[j])); }
    float2 mc = blockMax2(lm, lc);
    float s_mem = mkscale(mc.x), r_mem = 1.0f / s_mem;
    float s_cf  = mkscale(mc.y), r_cf  = 1.0f / s_cf;

    float cn[4]; float ln = 0.f;
    #pragma unroll
    for (int j = 0; j < 4; j++) {
        cn[j] = qvalr(cf[j], s_cf, r_cf) + qvalr(mem[j], s_mem, r_mem);  // Q(c*zf)+Q(z*zi)
        ln = fmaxf(ln, fabsf(cn[j]));
    }
    float cnmax = blockMax(ln);
    float s_cn  = mkscale(cnmax), r_cn = 1.0f / s_cn;

    // analytic: max|tanh(Q(cn))| = tanh(Q(max|cn|))
    float s_t = mkscale(tanhf(qvalr(cnmax, s_cn, r_cn)));
    float r_t = 1.0f / s_t;

    float zop[4] = { zo.x, zo.y, zo.z, zo.w };
    float hv[4]; float lh = 0.f;
    #pragma unroll
    for (int j = 0; j < 4; j++) {
        float cq = qvalr(cn[j], s_cn, r_cn);             // c_new
        float tq = qvalr(tanhf(cq), s_t, r_t);           // Q(tanh(c_new))
        hv[j] = zop[j] * tq;
        lh = fmaxf(lh, fabsf(hv[j]));
    }
    float s_h = mkscale(blockMax(lh)), r_h = 1.0f / s_h;

    float4 o;
    o.x = qvalr(hv[0], s_h, r_h); o.y = qvalr(hv[1], s_h, r_h);
    o.z = qvalr(hv[2], s_h, r_h); o.w = qvalr(hv[3], s_h, r_h);
    reinterpret_cast<float4*>(out)[t] = o;
}

// ---------------- launch ----------------
extern "C" void kernel_launch(void* const* d_in, const int* in_sizes, int n_in,
                              void* d_out, int out_size)
{
    const float* x  = (const float*)d_in[0];   // inputs (1, 4096)
    const float* c  = (const float*)d_in[1];   // c      (1, 4096)
    const float* h  = (const float*)d_in[2];   // h      (1, 4096)
    const float* Wf = (const float*)d_in[3];   // (8192, 4096)
    const float* bf = (const float*)d_in[4];   // (4096,)
    const float* Wi = (const float*)d_in[5];
    const float* bi = (const float*)d_in[6];
    const float* Wc = (const float*)d_in[7];
    const float* bc = (const float*)d_in[8];
    const float* Wo = (const float*)d_in[9];
    const float* bo = (const float*)d_in[10];

    prep_kernel<<<1, 1024>>>(x, h);

    dim3 gridB(D / 1024, KS, 4);               // (4, 32, 4) = 512 blocks
    gemv_kernel<<<gridB, 256>>>(x, h, Wf, Wi, Wc, Wo);

    gate_tail_kernel<<<4, 1024>>>(bf, bi, bc, bo, c, (float*)d_out);
}

// round 6
// speedup vs baseline: 1.0441x; 1.0441x over previous
#include <cuda_runtime.h>
#include <math.h>

#define D  4096
#define K2 8192
#define KS 32          // split-K chunks
#define KC (K2 / KS)   // 256 rows per chunk
#define NB 8           // n-chunks of 512 cols  -> grid (8,32,4) = 1024 blocks

// ---------------- scratch (no device allocation allowed) ----------------
__device__ float    g_partial[4 * KS * D];   // split-K partial sums (2 MB, L2-resident)
__device__ float    g_qa[4 * D];             // quantized gate activations (f, i, c, o)
__device__ unsigned g_done;                  // gate-block completion counter (zero-init)

// ---------------- helpers ----------------
__device__ __forceinline__ float mkscale(float maxabs) {
    // matches jnp.where(max_abs > 0, max_abs / 127.0, 1.0) in fp32
    return (maxabs > 0.0f) ? (maxabs / 127.0f) : 1.0f;
}

// quantize with precomputed reciprocal (one division per scale, FMA per element)
__device__ __forceinline__ float qvalr(float x, float scale, float rscale) {
    float r = rintf(x * rscale);
    r = fminf(fmaxf(r, -127.0f), 127.0f);
    return r * scale;
}

__device__ __forceinline__ float sigm(float x) {
    return __fdividef(1.0f, 1.0f + __expf(-x));
}

// Block-wide max (signed-safe). blockDim.x multiple of 32.
__device__ __forceinline__ float blockMax(float v) {
    __shared__ float s[32];
    const unsigned full = 0xffffffffu;
    #pragma unroll
    for (int o = 16; o; o >>= 1) v = fmaxf(v, __shfl_xor_sync(full, v, o));
    int lane = threadIdx.x & 31;
    int w    = threadIdx.x >> 5;
    int nw   = (blockDim.x + 31) >> 5;
    if (lane == 0) s[w] = v;
    __syncthreads();
    if (w == 0) {
        float r = (lane < nw) ? s[lane] : -INFINITY;
        #pragma unroll
        for (int o = 16; o; o >>= 1) r = fmaxf(r, __shfl_xor_sync(full, r, o));
        if (lane == 0) s[0] = r;
    }
    __syncthreads();
    float out = s[0];
    __syncthreads();
    return out;
}

// Two block-wide maxes sharing one set of barriers.
__device__ __forceinline__ float2 blockMax2(float a, float b) {
    __shared__ float sa[32], sb[32];
    const unsigned full = 0xffffffffu;
    #pragma unroll
    for (int o = 16; o; o >>= 1) {
        a = fmaxf(a, __shfl_xor_sync(full, a, o));
        b = fmaxf(b, __shfl_xor_sync(full, b, o));
    }
    int lane = threadIdx.x & 31;
    int w    = threadIdx.x >> 5;
    int nw   = (blockDim.x + 31) >> 5;
    if (lane == 0) { sa[w] = a; sb[w] = b; }
    __syncthreads();
    if (w == 0) {
        float ra = (lane < nw) ? sa[lane] : -INFINITY;
        float rb = (lane < nw) ? sb[lane] : -INFINITY;
        #pragma unroll
        for (int o = 16; o; o >>= 1) {
            ra = fmaxf(ra, __shfl_xor_sync(full, ra, o));
            rb = fmaxf(rb, __shfl_xor_sync(full, rb, o));
        }
        if (lane == 0) { sa[0] = ra; sb[0] = rb; }
    }
    __syncthreads();
    float2 out = make_float2(sa[0], sb[0]);
    __syncthreads();
    return out;
}

__device__ __forceinline__ float max4abs(float4 v) {
    return fmaxf(fmaxf(fabsf(v.x), fabsf(v.y)), fmaxf(fabsf(v.z), fabsf(v.w)));
}

// ---------------- kernel 1: fused concat-quant + split-K GEMV (HBM-bound) ----------------
// grid = (NB=8, KS=32, 4) = 1024 blocks x 256 threads, 2 cols/thread (float2).
// R5 lesson: the in-block concat-max prologue is free (overlaps the HBM stream),
// so no separate prep kernel. R3 lesson: need many blocks; this shape gives
// ~55 warps/SM (occ ~86%) to raise outstanding-load count -> DRAM duty cycle.
__global__ void __launch_bounds__(256) gemv_kernel(
    const float* __restrict__ x,  const float* __restrict__ h,
    const float* __restrict__ Wf, const float* __restrict__ Wi,
    const float* __restrict__ Wc, const float* __restrict__ Wo)
{
    __shared__ float xs[KC];
    const int g  = blockIdx.z;                              // gate
    const int kc = blockIdx.y;                              // k-chunk
    const int n0 = blockIdx.x * 512 + threadIdx.x * 2;      // 2 cols per thread
    const int k0 = kc * KC;

    const float* W = (g == 0) ? Wf : (g == 1) ? Wi : (g == 2) ? Wc : Wo;

    // global max of |[h, x]| (identical in every block -> consistent quantization)
    float lm = 0.0f;
    #pragma unroll
    for (int j = 0; j < K2 / 256; j++) {
        int i = threadIdx.x + j * 256;
        float v = (i < D) ? h[i] : x[i - D];
        lm = fmaxf(lm, fabsf(v));
    }
    float scale = mkscale(blockMax(lm));
    float rs = 1.0f / scale;

    // quantize this block's k-chunk of the concat (KC == blockDim.x == 256)
    {
        int gi = k0 + threadIdx.x;
        float v = (gi < D) ? h[gi] : x[gi - D];
        xs[threadIdx.x] = qvalr(v, scale, rs);
    }
    __syncthreads();

    const float2* p = reinterpret_cast<const float2*>(W + (size_t)k0 * D) + (n0 >> 1);
    const int rowstride = D / 2;

    float2 acc = make_float2(0.f, 0.f);
    #pragma unroll 8
    for (int i = 0; i < KC; i++) {
        float2 w = __ldcs(p + (size_t)i * rowstride);   // streaming: read-once weights
        float  xv = xs[i];
        acc.x = fmaf(xv, w.x, acc.x);
        acc.y = fmaf(xv, w.y, acc.y);
    }
    *reinterpret_cast<float2*>(&g_partial[(size_t)(g * KS + kc) * D + n0]) = acc;
}

// ---------------- kernel 2: gate chain (4 blocks) + fused tail in last-done block ----
__global__ void gate_tail_kernel(const float* __restrict__ bf, const float* __restrict__ bi,
                                 const float* __restrict__ bc, const float* __restrict__ bo,
                                 const float* __restrict__ c_in, float* __restrict__ out)
{
    const int g = blockIdx.x;
    const float* b = (g == 0) ? bf : (g == 1) ? bi : (g == 2) ? bc : bo;

    // --- per-gate: split-K reduce (L2-resident), quantized linear, activation ---
    const float4* pp = reinterpret_cast<const float4*>(g_partial)
                     + (size_t)g * KS * (D / 4) + threadIdx.x;
    float4 acc = make_float4(0.f, 0.f, 0.f, 0.f);
    #pragma unroll
    for (int ks = 0; ks < KS; ks++) {
        float4 v = pp[(size_t)ks * (D / 4)];
        acc.x += v.x; acc.y += v.y; acc.z += v.z; acc.w += v.w;
    }
    float4 bv = reinterpret_cast<const float4*>(b)[threadIdx.x];

    float2 mm = blockMax2(max4abs(acc), max4abs(bv));
    float sm = mkscale(mm.x), rsm = 1.0f / sm;     // Q(x@w) scale
    float sb = mkscale(mm.y), rsb = 1.0f / sb;     // Q(b) scale

    float y[4] = { qvalr(acc.x, sm, rsm) + qvalr(bv.x, sb, rsb),
                   qvalr(acc.y, sm, rsm) + qvalr(bv.y, sb, rsb),
                   qvalr(acc.z, sm, rsm) + qvalr(bv.z, sb, rsb),
                   qvalr(acc.w, sm, rsm) + qvalr(bv.w, sb, rsb) };

    float lmax = fmaxf(fmaxf(y[0], y[1]), fmaxf(y[2], y[3]));
    float lmin = fminf(fminf(y[0], y[1]), fminf(y[2], y[3]));
    float2 ym = blockMax2(lmax, -lmin);            // (max y, -min y)
    float sy  = mkscale(fmaxf(ym.x, ym.y));
    float rsy = 1.0f / sy;

    // analytic activation scale (monotone functions -> evaluate at argmax)
    float sa;
    if (g == 2) {
        sa = mkscale(tanhf(qvalr(fmaxf(ym.x, ym.y), sy, rsy)));  // tanh odd+monotone
    } else {
        sa = mkscale(sigm(qvalr(ym.x, sy, rsy)));                // sigmoid increasing, >0
    }
    float rsa = 1.0f / sa;

    float4 qa;
    float* qp = &qa.x;
    #pragma unroll
    for (int j = 0; j < 4; j++) {
        float yq = qvalr(y[j], sy, rsy);                 // Q(Q(x@w)+Q(b))
        float a  = (g == 2) ? tanhf(yq) : sigm(yq);
        qp[j] = qvalr(a, sa, rsa);                       // Q(activation)
    }
    reinterpret_cast<float4*>(g_qa)[(size_t)g * (D / 4) + threadIdx.x] = qa;

    // --- last-done handshake: the 4th block to finish runs the tail inline ---
    __shared__ unsigned s_ticket;
    __threadfence();                 // make this block's qa globally visible
    __syncthreads();                 // all threads' qa written + fenced
    if (threadIdx.x == 0) s_ticket = atomicAdd(&g_done, 1u);
    __syncthreads();
    if (s_ticket != 3u) return;      // not last: done
    __threadfence();                 // acquire: other blocks' qa now visible

    // --- tail: LSTM state update (this block only) ---
    const int t = threadIdx.x;
    const float4* qa4 = reinterpret_cast<const float4*>(g_qa);
    float4 zf = qa4[0 * (D / 4) + t];
    float4 zi = qa4[1 * (D / 4) + t];
    float4 z  = qa4[2 * (D / 4) + t];
    float4 zo = qa4[3 * (D / 4) + t];
    float4 cv = reinterpret_cast<const float4*>(c_in)[t];

    float mem[4] = { z.x * zi.x,  z.y * zi.y,  z.z * zi.z,  z.w * zi.w };
    float cf [4] = { cv.x * zf.x, cv.y * zf.y, cv.z * zf.z, cv.w * zf.w };

    float lm = 0.f, lc = 0.f;
    #pragma unroll
    for (int j = 0; j < 4; j++) { lm = fmaxf(lm, fabsf(mem[j])); lc = fmaxf(lc, fabsf(cf[j])); }
    float2 mc = blockMax2(lm, lc);
    float s_mem = mkscale(mc.x), r_mem = 1.0f / s_mem;
    float s_cf  = mkscale(mc.y), r_cf  = 1.0f / s_cf;

    float cn[4]; float ln = 0.f;
    #pragma unroll
    for (int j = 0; j < 4; j++) {
        cn[j] = qvalr(cf[j], s_cf, r_cf) + qvalr(mem[j], s_mem, r_mem);  // Q(c*zf)+Q(z*zi)
        ln = fmaxf(ln, fabsf(cn[j]));
    }
    float cnmax = blockMax(ln);
    float s_cn  = mkscale(cnmax), r_cn = 1.0f / s_cn;

    // analytic: max|tanh(Q(cn))| = tanh(Q(max|cn|))
    float s_t = mkscale(tanhf(qvalr(cnmax, s_cn, r_cn)));
    float r_t = 1.0f / s_t;

    float zop[4] = { zo.x, zo.y, zo.z, zo.w };
    float hv[4]; float lh = 0.f;
    #pragma unroll
    for (int j = 0; j < 4; j++) {
        float cq = qvalr(cn[j], s_cn, r_cn);             // c_new
        float tq = qvalr(tanhf(cq), s_t, r_t);           // Q(tanh(c_new))
        hv[j] = zop[j] * tq;
        lh = fmaxf(lh, fabsf(hv[j]));
    }
    float s_h = mkscale(blockMax(lh)), r_h = 1.0f / s_h;

    float4 o;
    o.x = qvalr(hv[0], s_h, r_h); o.y = qvalr(hv[1], s_h, r_h);
    o.z = qvalr(hv[2], s_h, r_h); o.w = qvalr(hv[3], s_h, r_h);
    reinterpret_cast<float4*>(out)[t] = o;

    // reset handshake for the next graph replay (only this block is alive here)
    __syncthreads();
    if (t == 0) g_done = 0u;
}

// ---------------- launch ----------------
extern "C" void kernel_launch(void* const* d_in, const int* in_sizes, int n_in,
                              void* d_out, int out_size)
{
    const float* x  = (const float*)d_in[0];   // inputs (1, 4096)
    const float* c  = (const float*)d_in[1];   // c      (1, 4096)
    const float* h  = (const float*)d_in[2];   // h      (1, 4096)
    const float* Wf = (const float*)d_in[3];   // (8192, 4096)
    const float* bf = (const float*)d_in[4];   // (4096,)
    const float* Wi = (const float*)d_in[5];
    const float* bi = (const float*)d_in[6];
    const float* Wc = (const float*)d_in[7];
    const float* bc = (const float*)d_in[8];
    const float* Wo = (const float*)d_in[9];
    const float* bo = (const float*)d_in[10];

    dim3 gridB(NB, KS, 4);                     // (8, 32, 4) = 1024 blocks
    gemv_kernel<<<gridB, 256>>>(x, h, Wf, Wi, Wc, Wo);

    gate_tail_kernel<<<4, 1024>>>(bf, bi, bc, bo, c, (float*)d_out);
}

// round 7
// speedup vs baseline: 1.0587x; 1.0140x over previous
#include <cuda_runtime.h>
#include <math.h>

#define D  4096
#define K2 8192
#define KS 32          // split-K chunks
#define KC (K2 / KS)   // 256 rows per chunk
#define NB 8           // n-chunks of 512 cols  -> grid (8,32,4) = 1024 blocks

// ---------------- scratch (no device allocation allowed) ----------------
__device__ float    g_partial[4 * KS * D];   // split-K partial sums (2 MB, L2-resident)
__device__ float    g_qa[4 * D];             // quantized gate activations (f, i, c, o)
__device__ unsigned g_done;                  // gate-block completion counter (zero-init)

// ---------------- helpers ----------------
__device__ __forceinline__ float mkscale(float maxabs) {
    // matches jnp.where(max_abs > 0, max_abs / 127.0, 1.0) in fp32
    return (maxabs > 0.0f) ? (maxabs / 127.0f) : 1.0f;
}

// quantize with precomputed reciprocal (one division per scale, FMA per element)
__device__ __forceinline__ float qvalr(float x, float scale, float rscale) {
    float r = rintf(x * rscale);
    r = fminf(fmaxf(r, -127.0f), 127.0f);
    return r * scale;
}

__device__ __forceinline__ float sigm(float x) {
    return __fdividef(1.0f, 1.0f + __expf(-x));
}

// Block-wide max (signed-safe). blockDim.x multiple of 32.
__device__ __forceinline__ float blockMax(float v) {
    __shared__ float s[32];
    const unsigned full = 0xffffffffu;
    #pragma unroll
    for (int o = 16; o; o >>= 1) v = fmaxf(v, __shfl_xor_sync(full, v, o));
    int lane = threadIdx.x & 31;
    int w    = threadIdx.x >> 5;
    int nw   = (blockDim.x + 31) >> 5;
    if (lane == 0) s[w] = v;
    __syncthreads();
    if (w == 0) {
        float r = (lane < nw) ? s[lane] : -INFINITY;
        #pragma unroll
        for (int o = 16; o; o >>= 1) r = fmaxf(r, __shfl_xor_sync(full, r, o));
        if (lane == 0) s[0] = r;
    }
    __syncthreads();
    float out = s[0];
    __syncthreads();
    return out;
}

// Two block-wide maxes sharing one set of barriers.
__device__ __forceinline__ float2 blockMax2(float a, float b) {
    __shared__ float sa[32], sb[32];
    const unsigned full = 0xffffffffu;
    #pragma unroll
    for (int o = 16; o; o >>= 1) {
        a = fmaxf(a, __shfl_xor_sync(full, a, o));
        b = fmaxf(b, __shfl_xor_sync(full, b, o));
    }
    int lane = threadIdx.x & 31;
    int w    = threadIdx.x >> 5;
    int nw   = (blockDim.x + 31) >> 5;
    if (lane == 0) { sa[w] = a; sb[w] = b; }
    __syncthreads();
    if (w == 0) {
        float ra = (lane < nw) ? sa[lane] : -INFINITY;
        float rb = (lane < nw) ? sb[lane] : -INFINITY;
        #pragma unroll
        for (int o = 16; o; o >>= 1) {
            ra = fmaxf(ra, __shfl_xor_sync(full, ra, o));
            rb = fmaxf(rb, __shfl_xor_sync(full, rb, o));
        }
        if (lane == 0) { sa[0] = ra; sb[0] = rb; }
    }
    __syncthreads();
    float2 out = make_float2(sa[0], sb[0]);
    __syncthreads();
    return out;
}

__device__ __forceinline__ float max4abs(float4 v) {
    return fmaxf(fmaxf(fabsf(v.x), fabsf(v.y)), fmaxf(fabsf(v.z), fabsf(v.w)));
}

// ---------------- kernel 1: fused concat-quant + split-K GEMV (HBM-bound) ----------------
// grid = (NB=8, KS=32, 4) = 1024 blocks x 256 threads, 2 cols/thread (float2).
// Measured ~77us (~7 TB/s) — at the HBM practical ceiling; DO NOT reshape.
__global__ void __launch_bounds__(256) gemv_kernel(
    const float* __restrict__ x,  const float* __restrict__ h,
    const float* __restrict__ Wf, const float* __restrict__ Wi,
    const float* __restrict__ Wc, const float* __restrict__ Wo)
{
    __shared__ float xs[KC];
    const int g  = blockIdx.z;                              // gate
    const int kc = blockIdx.y;                              // k-chunk
    const int n0 = blockIdx.x * 512 + threadIdx.x * 2;      // 2 cols per thread
    const int k0 = kc * KC;

    const float* W = (g == 0) ? Wf : (g == 1) ? Wi : (g == 2) ? Wc : Wo;

    // global max of |[h, x]| (identical in every block -> consistent quantization)
    float lm = 0.0f;
    #pragma unroll
    for (int j = 0; j < K2 / 256; j++) {
        int i = threadIdx.x + j * 256;
        float v = (i < D) ? h[i] : x[i - D];
        lm = fmaxf(lm, fabsf(v));
    }
    float scale = mkscale(blockMax(lm));
    float rs = 1.0f / scale;

    // quantize this block's k-chunk of the concat (KC == blockDim.x == 256)
    {
        int gi = k0 + threadIdx.x;
        float v = (gi < D) ? h[gi] : x[gi - D];
        xs[threadIdx.x] = qvalr(v, scale, rs);
    }
    __syncthreads();

    const float2* p = reinterpret_cast<const float2*>(W + (size_t)k0 * D) + (n0 >> 1);
    const int rowstride = D / 2;

    float2 acc = make_float2(0.f, 0.f);
    #pragma unroll 8
    for (int i = 0; i < KC; i++) {
        float2 w = __ldcs(p + (size_t)i * rowstride);   // streaming: read-once weights
        float  xv = xs[i];
        acc.x = fmaf(xv, w.x, acc.x);
        acc.y = fmaf(xv, w.y, acc.y);
    }
    *reinterpret_cast<float2*>(&g_partial[(size_t)(g * KS + kc) * D + n0]) = acc;
}

// ---------------- kernel 2: gate chain (4 blocks) + fused tail in last-done block ----
// __launch_bounds__(1024, 1): allow up to 64 regs/thread so the 32 independent
// L2 loads of the split-K reduce can be deeply pipelined (R6: regs=32 ->
// long-scoreboard serialization, 15.9us).
__global__ void __launch_bounds__(1024, 1)
gate_tail_kernel(const float* __restrict__ bf, const float* __restrict__ bi,
                 const float* __restrict__ bc, const float* __restrict__ bo,
                 const float* __restrict__ c_in, float* __restrict__ out)
{
    const int g = blockIdx.x;
    const float* b = (g == 0) ? bf : (g == 1) ? bi : (g == 2) ? bc : bo;
    const int t = threadIdx.x;

    // preload c (every block: the eventual tail winner then has it in registers)
    float4 cv = reinterpret_cast<const float4*>(c_in)[t];
    float4 bv = reinterpret_cast<const float4*>(b)[t];

    // --- split-K reduce: 4 independent accumulator chains, fully unrolled ---
    const float4* pp = reinterpret_cast<const float4*>(g_partial)
                     + (size_t)g * KS * (D / 4) + t;
    float4 a0 = make_float4(0.f, 0.f, 0.f, 0.f);
    float4 a1 = make_float4(0.f, 0.f, 0.f, 0.f);
    float4 a2 = make_float4(0.f, 0.f, 0.f, 0.f);
    float4 a3 = make_float4(0.f, 0.f, 0.f, 0.f);
    #pragma unroll
    for (int ks = 0; ks < KS; ks += 4) {
        float4 v0 = pp[(size_t)(ks + 0) * (D / 4)];
        float4 v1 = pp[(size_t)(ks + 1) * (D / 4)];
        float4 v2 = pp[(size_t)(ks + 2) * (D / 4)];
        float4 v3 = pp[(size_t)(ks + 3) * (D / 4)];
        a0.x += v0.x; a0.y += v0.y; a0.z += v0.z; a0.w += v0.w;
        a1.x += v1.x; a1.y += v1.y; a1.z += v1.z; a1.w += v1.w;
        a2.x += v2.x; a2.y += v2.y; a2.z += v2.z; a2.w += v2.w;
        a3.x += v3.x; a3.y += v3.y; a3.z += v3.z; a3.w += v3.w;
    }
    float4 acc;
    acc.x = (a0.x + a1.x) + (a2.x + a3.x);
    acc.y = (a0.y + a1.y) + (a2.y + a3.y);
    acc.z = (a0.z + a1.z) + (a2.z + a3.z);
    acc.w = (a0.w + a1.w) + (a2.w + a3.w);

    float2 mm = blockMax2(max4abs(acc), max4abs(bv));
    float sm = mkscale(mm.x), rsm = 1.0f / sm;     // Q(x@w) scale
    float sb = mkscale(mm.y), rsb = 1.0f / sb;     // Q(b) scale

    // y = Q(x@w) + Q(b)
    float y[4] = { qvalr(acc.x, sm, rsm) + qvalr(bv.x, sb, rsb),
                   qvalr(acc.y, sm, rsm) + qvalr(bv.y, sb, rsb),
                   qvalr(acc.z, sm, rsm) + qvalr(bv.z, sb, rsb),
                   qvalr(acc.w, sm, rsm) + qvalr(bv.w, sb, rsb) };

    float lmax = fmaxf(fmaxf(y[0], y[1]), fmaxf(y[2], y[3]));
    float lmin = fminf(fminf(y[0], y[1]), fminf(y[2], y[3]));
    float2 ym = blockMax2(lmax, -lmin);            // (max y, -min y)
    float sy  = mkscale(fmaxf(ym.x, ym.y));
    float rsy = 1.0f / sy;

    // analytic activation scale (monotone functions -> evaluate at argmax)
    float sa;
    if (g == 2) {
        sa = mkscale(tanhf(qvalr(fmaxf(ym.x, ym.y), sy, rsy)));  // tanh odd+monotone
    } else {
        sa = mkscale(sigm(qvalr(ym.x, sy, rsy)));                // sigmoid increasing, >0
    }
    float rsa = 1.0f / sa;

    float4 qa;
    float* qp = &qa.x;
    #pragma unroll
    for (int j = 0; j < 4; j++) {
        float yq = qvalr(y[j], sy, rsy);                 // Q(Q(x@w)+Q(b))
        float a  = (g == 2) ? tanhf(yq) : sigm(yq);
        qp[j] = qvalr(a, sa, rsa);                       // Q(activation)
    }
    reinterpret_cast<float4*>(g_qa)[(size_t)g * (D / 4) + t] = qa;

    // --- last-done handshake: the 4th block to finish runs the tail inline ---
    __shared__ unsigned s_ticket;
    __threadfence();                 // make this block's qa globally visible
    __syncthreads();                 // all threads' qa written + fenced
    if (t == 0) s_ticket = atomicAdd(&g_done, 1u);
    __syncthreads();
    if (s_ticket != 3u) return;      // not last: done
    __threadfence();                 // acquire: other blocks' qa now visible

    // --- tail: LSTM state update (this block only; own gate's qa already in regs) ---
    const float4* qa4 = reinterpret_cast<const float4*>(g_qa);
    float4 zf = (g == 0) ? qa : qa4[0 * (D / 4) + t];
    float4 zi = (g == 1) ? qa : qa4[1 * (D / 4) + t];
    float4 z  = (g == 2) ? qa : qa4[2 * (D / 4) + t];
    float4 zo = (g == 3) ? qa : qa4[3 * (D / 4) + t];

    float mem[4] = { z.x * zi.x,  z.y * zi.y,  z.z * zi.z,  z.w * zi.w };
    float cf [4] = { cv.x * zf.x, cv.y * zf.y, cv.z * zf.z, cv.w * zf.w };

    float lm = 0.f, lc = 0.f;
    #pragma unroll
    for (int j = 0; j < 4; j++) { lm = fmaxf(lm, fabsf(mem[j])); lc = fmaxf(lc, fabsf(cf[j])); }
    float2 mc = blockMax2(lm, lc);
    float s_mem = mkscale(mc.x), r_mem = 1.0f / s_mem;
    float s_cf  = mkscale(mc.y), r_cf  = 1.0f / s_cf;

    float cn[4]; float ln = 0.f;
    #pragma unroll
    for (int j = 0; j < 4; j++) {
        cn[j] = qvalr(cf[j], s_cf, r_cf) + qvalr(mem[j], s_mem, r_mem);  // Q(c*zf)+Q(z*zi)
        ln = fmaxf(ln, fabsf(cn[j]));
    }
    float cnmax = blockMax(ln);
    float s_cn  = mkscale(cnmax), r_cn = 1.0f / s_cn;

    // analytic: max|tanh(Q(cn))| = tanh(Q(max|cn|))
    float s_t = mkscale(tanhf(qvalr(cnmax, s_cn, r_cn)));
    float r_t = 1.0f / s_t;

    float zop[4] = { zo.x, zo.y, zo.z, zo.w };
    float hv[4]; float lh = 0.f;
    #pragma unroll
    for (int j = 0; j < 4; j++) {
        float cq = qvalr(cn[j], s_cn, r_cn);             // c_new
        float tq = qvalr(tanhf(cq), s_t, r_t);           // Q(tanh(c_new))
        hv[j] = zop[j] * tq;
        lh = fmaxf(lh, fabsf(hv[j]));
    }
    float s_h = mkscale(blockMax(lh)), r_h = 1.0f / s_h;

    float4 o;
    o.x = qvalr(hv[0], s_h, r_h); o.y = qvalr(hv[1], s_h, r_h);
    o.z = qvalr(hv[2], s_h, r_h); o.w = qvalr(hv[3], s_h, r_h);
    reinterpret_cast<float4*>(out)[t] = o;

    // reset handshake for the next graph replay (only this block is alive here)
    __syncthreads();
    if (t == 0) g_done = 0u;
}

// ---------------- launch ----------------
extern "C" void kernel_launch(void* const* d_in, const int* in_sizes, int n_in,
                              void* d_out, int out_size)
{
    const float* x  = (const float*)d_in[0];   // inputs (1, 4096)
    const float* c  = (const float*)d_in[1];   // c      (1, 4096)
    const float* h  = (const float*)d_in[2];   // h      (1, 4096)
    const float* Wf = (const float*)d_in[3];   // (8192, 4096)
    const float* bf = (const float*)d_in[4];   // (4096,)
    const float* Wi = (const float*)d_in[5];
    const float* bi = (const float*)d_in[6];
    const float* Wc = (const float*)d_in[7];
    const float* bc = (const float*)d_in[8];
    const float* Wo = (const float*)d_in[9];
    const float* bo = (const float*)d_in[10];

    dim3 gridB(NB, KS, 4);                     // (8, 32, 4) = 1024 blocks
    gemv_kernel<<<gridB, 256>>>(x, h, Wf, Wi, Wc, Wo);

    gate_tail_kernel<<<4, 1024>>>(bf, bi, bc, bo, c, (float*)d_out);
}